// round 2
// baseline (speedup 1.0000x reference)
#include <cuda_runtime.h>
#include <math.h>

#define BSZ 4096
#define FDIM 768
#define PDIM 500
#define ZDIM 300
#define RNUM 10
#define NRET (BSZ * RNUM)          // 40960
#define EDGE_ROWS (BSZ * 4)        // 16384
#define M_ROWS (EDGE_ROWS + RNUM)  // 16394 (4 edge-means/sample + 10 sample-0 pair means)
#define FEATD 2100
#define H1D 800
#define H2D 200

// ---------------- scratch (device globals; no allocation allowed) ----------------
__device__ float g_Rout[3ull * NRET * PDIM];   // tanh embeddings: [rt, rv, ru] x [40960, 500]
__device__ float g_E[6ull * BSZ * PDIM];       // per-sample: emb_t, emb_v, emb_u, S_rt, S_rv, S_ru
__device__ float g_M[(size_t)M_ROWS * PDIM];   // edge means (+ pair means)
__device__ float g_Y[(size_t)M_ROWS * ZDIM];   // hg-projected edge features
__device__ float g_feat[(size_t)BSZ * FEATD];
__device__ float g_h1[(size_t)BSZ * H1D];
__device__ float g_h2[(size_t)BSZ * H2D];

// ---------------- generic tiled SGEMM: C = epi(A @ W^T + bias) ----------------
// A: [M,K] row-major, W: [N,K] row-major, C: [M,N]. BM=128, BN=64, BK=16, 256 thr, 8x4/thread.
template <int EPI>  // 0=none, 1=tanh, 2=relu
__global__ void __launch_bounds__(256) sgemm(const float* __restrict__ A,
                                             const float* __restrict__ W,
                                             const float* __restrict__ bias,
                                             float* __restrict__ C,
                                             int M, int N, int K) {
    __shared__ float As[16][128];
    __shared__ float Wsm[16][64];

    const int tid = threadIdx.x;
    const int tx = tid & 15;   // -> n (tx*4)
    const int ty = tid >> 4;   // -> m (ty*8)
    const int bm = blockIdx.y * 128;
    const int bn = blockIdx.x * 64;

    const int lr = tid >> 2;         // 0..63
    const int lk = (tid & 3) * 4;    // 0,4,8,12

    float acc[8][4];
#pragma unroll
    for (int i = 0; i < 8; i++)
#pragma unroll
        for (int j = 0; j < 4; j++) acc[i][j] = 0.f;

    const int ntiles = (K + 15) >> 4;
    for (int t = 0; t < ntiles; t++) {
        const int k0 = t * 16;
        const int gk = k0 + lk;
        // --- load A tile (128x16): 2 float4 per thread ---
#pragma unroll
        for (int rr = 0; rr < 2; rr++) {
            const int r = lr + rr * 64;
            const int gm = bm + r;
            float4 v = make_float4(0.f, 0.f, 0.f, 0.f);
            if (gm < M) {
                if (gk + 4 <= K) {
                    v = *reinterpret_cast<const float4*>(A + (size_t)gm * K + gk);
                } else {
                    float tmp[4] = {0.f, 0.f, 0.f, 0.f};
#pragma unroll
                    for (int q = 0; q < 4; q++)
                        if (gk + q < K) tmp[q] = A[(size_t)gm * K + gk + q];
                    v = make_float4(tmp[0], tmp[1], tmp[2], tmp[3]);
                }
            }
            As[lk + 0][r] = v.x; As[lk + 1][r] = v.y;
            As[lk + 2][r] = v.z; As[lk + 3][r] = v.w;
        }
        // --- load W tile (64x16): 1 float4 per thread ---
        {
            const int gn = bn + lr;
            float4 v = make_float4(0.f, 0.f, 0.f, 0.f);
            if (gn < N) {
                if (gk + 4 <= K) {
                    v = *reinterpret_cast<const float4*>(W + (size_t)gn * K + gk);
                } else {
                    float tmp[4] = {0.f, 0.f, 0.f, 0.f};
#pragma unroll
                    for (int q = 0; q < 4; q++)
                        if (gk + q < K) tmp[q] = W[(size_t)gn * K + gk + q];
                    v = make_float4(tmp[0], tmp[1], tmp[2], tmp[3]);
                }
            }
            Wsm[lk + 0][lr] = v.x; Wsm[lk + 1][lr] = v.y;
            Wsm[lk + 2][lr] = v.z; Wsm[lk + 3][lr] = v.w;
        }
        __syncthreads();
#pragma unroll
        for (int k = 0; k < 16; k++) {
            float ra[8], rb[4];
            *(float4*)&ra[0] = *(const float4*)&As[k][ty * 8];
            *(float4*)&ra[4] = *(const float4*)&As[k][ty * 8 + 4];
            *(float4*)&rb[0] = *(const float4*)&Wsm[k][tx * 4];
#pragma unroll
            for (int i = 0; i < 8; i++)
#pragma unroll
                for (int j = 0; j < 4; j++) acc[i][j] = fmaf(ra[i], rb[j], acc[i][j]);
        }
        __syncthreads();
    }

#pragma unroll
    for (int i = 0; i < 8; i++) {
        const int gm = bm + ty * 8 + i;
        if (gm >= M) continue;
#pragma unroll
        for (int j = 0; j < 4; j++) {
            const int gn = bn + tx * 4 + j;
            if (gn >= N) continue;
            float v = acc[i][j] + bias[gn];
            if (EPI == 1) v = tanhf(v);
            else if (EPI == 2) v = fmaxf(v, 0.f);
            C[(size_t)gm * N + gn] = v;
        }
    }
}

// ---------------- sum of 10 retrieved embeddings per sample ----------------
__global__ void reduce_retrieved() {
    const size_t idx = (size_t)blockIdx.x * blockDim.x + threadIdx.x;
    if (idx >= (size_t)BSZ * PDIM) return;
    const int s = blockIdx.y;  // 0=rt,1=rv,2=ru
    const int b = (int)(idx / PDIM), p = (int)(idx % PDIM);
    const float* base = g_Rout + (size_t)s * NRET * PDIM + (size_t)b * RNUM * PDIM + p;
    float sum = 0.f;
#pragma unroll
    for (int i = 0; i < RNUM; i++) sum += base[(size_t)i * PDIM];
    g_E[((size_t)(3 + s) * BSZ + b) * PDIM + p] = sum;
}

// ---------------- edge means in PD space ----------------
__global__ void build_means() {
    const size_t idx = (size_t)blockIdx.x * blockDim.x + threadIdx.x;
    if (idx >= (size_t)BSZ * PDIM) return;
    const int b = (int)(idx / PDIM), p = (int)(idx % PDIM);
    const float et = g_E[((size_t)0 * BSZ + b) * PDIM + p];
    const float ev = g_E[((size_t)1 * BSZ + b) * PDIM + p];
    const float eu = g_E[((size_t)2 * BSZ + b) * PDIM + p];
    const float srt = g_E[((size_t)3 * BSZ + b) * PDIM + p];
    const float srv = g_E[((size_t)4 * BSZ + b) * PDIM + p];
    const float sru = g_E[((size_t)5 * BSZ + b) * PDIM + p];
    float* row = g_M + (size_t)b * 4 * PDIM + p;
    row[0 * PDIM] = (et + ev + eu) * (1.f / 3.f);
    row[1 * PDIM] = (srt + et) * (1.f / 11.f);
    row[2 * PDIM] = (srv + ev) * (1.f / 11.f);
    row[3 * PDIM] = (sru + eu) * (1.f / 11.f);
}

// ---------------- sample-0 pair-edge means ----------------
__global__ void build_pair_means() {
    const int idx = blockIdx.x * blockDim.x + threadIdx.x;
    if (idx >= RNUM * PDIM) return;
    const int i = idx / PDIM, p = idx % PDIM;
    const float a = g_Rout[(size_t)0 * NRET * PDIM + (size_t)i * PDIM + p];  // sample0 rt_i
    const float c = g_Rout[(size_t)1 * NRET * PDIM + (size_t)i * PDIM + p];  // sample0 rv_i
    g_M[(size_t)(EDGE_ROWS + i) * PDIM + p] = 0.5f * (a + c);
}

// ---------------- assemble the 2100-d feature vector per sample ----------------
__global__ void build_feat(const float* __restrict__ similarity,
                           const float* __restrict__ rlabel,
                           const float* __restrict__ lbl_w,
                           const float* __restrict__ lbl_b) {
    const int b = blockIdx.x;
    __shared__ float ssim[RNUM];
    __shared__ float s_lbl;
    if (threadIdx.x == 0) {
        float v[RNUM], mx = -1e30f;
#pragma unroll
        for (int i = 0; i < RNUM; i++) { v[i] = similarity[b * RNUM + i]; mx = fmaxf(mx, v[i]); }
        float sum = 0.f;
#pragma unroll
        for (int i = 0; i < RNUM; i++) { v[i] = expf(v[i] - mx); sum += v[i]; }
        float la = 0.f;
        const float inv = 1.f / sum;
#pragma unroll
        for (int i = 0; i < RNUM; i++) {
            v[i] *= inv; ssim[i] = v[i];
            la += v[i] * rlabel[b * RNUM + i];
        }
        s_lbl = la;
    }
    __syncthreads();
    const float* Yb = g_Y + (size_t)b * 4 * ZDIM;
    float* fb = g_feat + (size_t)b * FEATD;
    const float lagg = s_lbl;
    for (int z = threadIdx.x; z < ZDIM; z += blockDim.x) {
        const float Y0 = Yb[z], Y1 = Yb[ZDIM + z], Y2 = Yb[2 * ZDIM + z], Y3 = Yb[3 * ZDIM + z];
        fb[z]            = fmaxf(0.5f * (Y0 + Y1), 0.f);  // Xo node0 (t)
        fb[ZDIM + z]     = fmaxf(0.5f * (Y0 + Y2), 0.f);  // Xo node1 (v)
        fb[2 * ZDIM + z] = fmaxf(0.5f * (Y0 + Y3), 0.f);  // Xo node2 (u)
        float rv, rt;
        if (b != 0) {
            rv = fmaxf(Y2, 0.f);  // softmax weights sum to 1 over identical rows
            rt = fmaxf(Y1, 0.f);
        } else {
            rv = 0.f; rt = 0.f;
#pragma unroll
            for (int i = 0; i < RNUM; i++) {
                const float yp = g_Y[(size_t)(EDGE_ROWS + i) * ZDIM + z];
                rt += ssim[i] * fmaxf(0.5f * (Y1 + yp), 0.f);
                rv += ssim[i] * fmaxf(0.5f * (Y2 + yp), 0.f);
            }
        }
        fb[3 * ZDIM + z] = rv;                           // rv_agg
        fb[4 * ZDIM + z] = rt;                           // rt_agg
        fb[5 * ZDIM + z] = fmaxf(Y3, 0.f);               // ru_agg (usim cancels)
        fb[6 * ZDIM + z] = fmaxf(lagg * lbl_w[z] + lbl_b[z], 0.f);  // lbl_emb
    }
}

// ---------------- final: sigmoid(h2 . p3_w + b), one warp per sample ----------------
__global__ void final_out(const float* __restrict__ p3_w, const float* __restrict__ p3_b,
                          float* __restrict__ out) {
    const int warp = (blockIdx.x * blockDim.x + threadIdx.x) >> 5;
    const int lane = threadIdx.x & 31;
    if (warp >= BSZ) return;
    const float* h = g_h2 + (size_t)warp * H2D;
    float s = 0.f;
    for (int j = lane; j < H2D; j += 32) s += h[j] * p3_w[j];
#pragma unroll
    for (int off = 16; off; off >>= 1) s += __shfl_xor_sync(0xffffffffu, s, off);
    if (lane == 0) out[warp] = 1.f / (1.f + expf(-(s + p3_b[0])));
}

// ---------------- host launcher ----------------
extern "C" void kernel_launch(void* const* d_in, const int* in_sizes, int n_in,
                              void* d_out, int out_size) {
    const float* vis   = (const float*)d_in[0];
    const float* txt   = (const float*)d_in[1];
    const float* sim   = (const float*)d_in[2];
    const float* rvis  = (const float*)d_in[3];
    const float* rtxt  = (const float*)d_in[4];
    const float* rlbl  = (const float*)d_in[5];
    const float* usr   = (const float*)d_in[6];
    const float* rusr  = (const float*)d_in[7];
    // d_in[8] retrieved_user_similarity: provably unused (softmax cancels)
    const float* vis_w = (const float*)d_in[9],  *vis_b = (const float*)d_in[10];
    const float* txt_w = (const float*)d_in[11], *txt_b = (const float*)d_in[12];
    const float* usr_w = (const float*)d_in[13], *usr_b = (const float*)d_in[14];
    const float* rvis_w = (const float*)d_in[15], *rvis_b = (const float*)d_in[16];
    const float* rtxt_w = (const float*)d_in[17], *rtxt_b = (const float*)d_in[18];
    const float* rusr_w = (const float*)d_in[19], *rusr_b = (const float*)d_in[20];
    const float* hg_w  = (const float*)d_in[21], *hg_b = (const float*)d_in[22];
    const float* lbl_w = (const float*)d_in[23], *lbl_b = (const float*)d_in[24];
    const float* p1_w  = (const float*)d_in[25], *p1_b = (const float*)d_in[26];
    const float* p2_w  = (const float*)d_in[27], *p2_b = (const float*)d_in[28];
    const float* p3_w  = (const float*)d_in[29], *p3_b = (const float*)d_in[30];

    float *Rout, *E, *Mb, *Y, *feat, *h1, *h2;
    cudaGetSymbolAddress((void**)&Rout, g_Rout);
    cudaGetSymbolAddress((void**)&E, g_E);
    cudaGetSymbolAddress((void**)&Mb, g_M);
    cudaGetSymbolAddress((void**)&Y, g_Y);
    cudaGetSymbolAddress((void**)&feat, g_feat);
    cudaGetSymbolAddress((void**)&h1, g_h1);
    cudaGetSymbolAddress((void**)&h2, g_h2);

    const dim3 blk(256);
    const dim3 gEmbS((PDIM + 63) / 64, (BSZ + 127) / 128);   // single-node embeds
    const dim3 gEmbR((PDIM + 63) / 64, (NRET + 127) / 128);  // retrieved embeds

    // 1) tanh embeddings (6 GEMM segments, fused tanh epilogue)
    sgemm<1><<<gEmbS, blk>>>(txt, txt_w, txt_b, E + (size_t)0 * BSZ * PDIM, BSZ, PDIM, FDIM);
    sgemm<1><<<gEmbS, blk>>>(vis, vis_w, vis_b, E + (size_t)1 * BSZ * PDIM, BSZ, PDIM, FDIM);
    sgemm<1><<<gEmbS, blk>>>(usr, usr_w, usr_b, E + (size_t)2 * BSZ * PDIM, BSZ, PDIM, FDIM);
    sgemm<1><<<gEmbR, blk>>>(rtxt, rtxt_w, rtxt_b, Rout + (size_t)0 * NRET * PDIM, NRET, PDIM, FDIM);
    sgemm<1><<<gEmbR, blk>>>(rvis, rvis_w, rvis_b, Rout + (size_t)1 * NRET * PDIM, NRET, PDIM, FDIM);
    sgemm<1><<<gEmbR, blk>>>(rusr, rusr_w, rusr_b, Rout + (size_t)2 * NRET * PDIM, NRET, PDIM, FDIM);

    // 2) sums over the 10 retrieved items per sample
    reduce_retrieved<<<dim3(((size_t)BSZ * PDIM + 255) / 256, 3), blk>>>();

    // 3) edge means (+ sample-0 pair means)
    build_means<<<((size_t)BSZ * PDIM + 255) / 256, blk>>>();
    build_pair_means<<<(RNUM * PDIM + 255) / 256, blk>>>();

    // 4) hypergraph projection: Y = M @ hg_w^T + hg_b
    sgemm<0><<<dim3((ZDIM + 63) / 64, (M_ROWS + 127) / 128), blk>>>(Mb, hg_w, hg_b, Y, M_ROWS, ZDIM, PDIM);

    // 5) feature assembly (softmax, aggregation, label embed)
    build_feat<<<BSZ, blk>>>(sim, rlbl, lbl_w, lbl_b);

    // 6) MLP head
    sgemm<2><<<dim3((H1D + 63) / 64, (BSZ + 127) / 128), blk>>>(feat, p1_w, p1_b, h1, BSZ, H1D, FEATD);
    sgemm<2><<<dim3((H2D + 63) / 64, (BSZ + 127) / 128), blk>>>(h1, p2_w, p2_b, h2, BSZ, H2D, H1D);
    final_out<<<(BSZ * 32 + 255) / 256, blk>>>(p3_w, p3_b, (float*)d_out);
}

// round 5
// speedup vs baseline: 2.1778x; 2.1778x over previous
#include <cuda_runtime.h>
#include <cuda_bf16.h>
#include <cstdint>
#include <math.h>

#define BSZ 4096
#define FDIM 768
#define PDIM 500
#define ZDIM 300
#define RNUM 10
#define NRET (BSZ * RNUM)          // 40960
#define EDGE_ROWS (BSZ * 4)        // 16384
#define M_ROWS (EDGE_ROWS + RNUM)  // 16394
#define FEATD 2100
#define H1D 800
#define H2D 200

// ---------------- scratch (device globals) ----------------
__device__ float g_Rout[3ull * NRET * PDIM];
__device__ float g_E[6ull * BSZ * PDIM];
__device__ float g_M[(size_t)M_ROWS * PDIM];
__device__ float g_Y[(size_t)M_ROWS * ZDIM];
__device__ float g_feat[(size_t)BSZ * FEATD];
__device__ float g_h1[(size_t)BSZ * H1D];
__device__ float g_h2[(size_t)BSZ * H2D];

// ---------------- warp-MMA helpers (portable since sm_80) ----------------
__device__ __forceinline__ uint32_t smem_u32(const void* p) {
    uint32_t a;
    asm("{ .reg .u64 t; cvta.to.shared.u64 t, %1; cvt.u32.u64 %0, t; }" : "=r"(a) : "l"(p));
    return a;
}
__device__ __forceinline__ void ldsm4(uint32_t* r, uint32_t addr) {
    asm volatile("ldmatrix.sync.aligned.m8n8.x4.shared.b16 {%0,%1,%2,%3}, [%4];"
                 : "=r"(r[0]), "=r"(r[1]), "=r"(r[2]), "=r"(r[3]) : "r"(addr));
}
__device__ __forceinline__ void mma16816(float* d, const uint32_t* a, uint32_t b0, uint32_t b1) {
    asm volatile(
        "mma.sync.aligned.m16n8k16.row.col.f32.bf16.bf16.f32 "
        "{%0,%1,%2,%3}, {%4,%5,%6,%7}, {%8,%9}, {%0,%1,%2,%3};"
        : "+f"(d[0]), "+f"(d[1]), "+f"(d[2]), "+f"(d[3])
        : "r"(a[0]), "r"(a[1]), "r"(a[2]), "r"(a[3]), "r"(b0), "r"(b1));
}
__device__ __forceinline__ uint32_t packbf(__nv_bfloat16 x, __nv_bfloat16 y) {
    __nv_bfloat162 t; t.x = x; t.y = y;
    return *reinterpret_cast<uint32_t*>(&t);
}
// 16B-chunk XOR swizzle for 64B rows: chunk' = chunk ^ ((row>>1)&3)
__device__ __forceinline__ uint32_t swz(int row, int chunk) {
    return (uint32_t)(row * 64 + ((chunk ^ ((row >> 1) & 3)) << 4));
}

#define STAGE_BYTES 32768  // Ahi 8K | Alo 8K | Whi 8K | Wlo 8K
#define SMEM_BYTES 65536

// ============ split-bf16 HMMA GEMM: C = epi(A[M,K] @ W[N,K]^T + bias) ============
// 3-pass: D = Ahi*Whi + Alo*Whi + Ahi*Wlo  (error ~2^-16)
template <int EPI>  // 0=none, 1=tanh, 2=relu
__global__ void __launch_bounds__(256, 1)
hgemm(const float* __restrict__ A, const float* __restrict__ W,
      const float* __restrict__ bias, float* __restrict__ C,
      int M, int N, int K) {
    extern __shared__ char smem[];
    const uint32_t sbase = smem_u32(smem);
    const int tid = threadIdx.x, wid = tid >> 5, lane = tid & 31;
    const int bm = blockIdx.y * 128, bn = blockIdx.x * 128;
    const int wm = (wid & 3) * 32;   // warp m offset
    const int wn = (wid >> 2) * 64;  // warp n offset

    float acc[16][4];
#pragma unroll
    for (int i = 0; i < 16; i++)
#pragma unroll
        for (int j = 0; j < 4; j++) acc[i][j] = 0.f;

    const int nch = (K + 31) >> 5;
    float4 pa[4], pw[4];

    auto loadg = [&](int c) {
        const int kk0 = c << 5;
#pragma unroll
        for (int i = 0; i < 4; i++) {
            const int slot = tid + (i << 8);
            const int row = slot >> 3, c4 = slot & 7;
            const int gk = kk0 + (c4 << 2);
            const int gm = bm + row;
            float4 v = make_float4(0.f, 0.f, 0.f, 0.f);
            if (gm < M) {
                if (gk + 4 <= K) v = *reinterpret_cast<const float4*>(A + (size_t)gm * K + gk);
                else {
                    float t[4] = {0.f, 0.f, 0.f, 0.f};
                    for (int q = 0; q < 4; q++) if (gk + q < K) t[q] = A[(size_t)gm * K + gk + q];
                    v = make_float4(t[0], t[1], t[2], t[3]);
                }
            }
            pa[i] = v;
            const int gn = bn + row;
            float4 w = make_float4(0.f, 0.f, 0.f, 0.f);
            if (gn < N) {
                if (gk + 4 <= K) w = *reinterpret_cast<const float4*>(W + (size_t)gn * K + gk);
                else {
                    float t[4] = {0.f, 0.f, 0.f, 0.f};
                    for (int q = 0; q < 4; q++) if (gk + q < K) t[q] = W[(size_t)gn * K + gk + q];
                    w = make_float4(t[0], t[1], t[2], t[3]);
                }
            }
            pw[i] = w;
        }
    };

    auto stores = [&](int st) {
        char* base = smem + st * STAGE_BYTES;
#pragma unroll
        for (int i = 0; i < 4; i++) {
            const int slot = tid + (i << 8);
            const int row = slot >> 3, c4 = slot & 7;
            const uint32_t byte = swz(row, c4 >> 1) + ((c4 & 1) << 3);
#pragma unroll
            for (int half = 0; half < 2; half++) {
                const float4 v = half ? pw[i] : pa[i];
                const __nv_bfloat16 h0 = __float2bfloat16(v.x), h1 = __float2bfloat16(v.y);
                const __nv_bfloat16 h2 = __float2bfloat16(v.z), h3 = __float2bfloat16(v.w);
                const __nv_bfloat16 l0 = __float2bfloat16(v.x - __bfloat162float(h0));
                const __nv_bfloat16 l1 = __float2bfloat16(v.y - __bfloat162float(h1));
                const __nv_bfloat16 l2 = __float2bfloat16(v.z - __bfloat162float(h2));
                const __nv_bfloat16 l3 = __float2bfloat16(v.w - __bfloat162float(h3));
                uint2 hi, lo;
                hi.x = packbf(h0, h1); hi.y = packbf(h2, h3);
                lo.x = packbf(l0, l1); lo.y = packbf(l2, l3);
                char* r = base + half * 16384;
                *reinterpret_cast<uint2*>(r + byte) = hi;
                *reinterpret_cast<uint2*>(r + 8192 + byte) = lo;
            }
        }
    };

    auto do_mma = [&](int st) {
        const uint32_t sA = sbase + st * STAGE_BYTES;
        const uint32_t sW = sA + 16384;
#pragma unroll
        for (int ks = 0; ks < 2; ks++) {
            uint32_t ah[2][4], al[2][4];
#pragma unroll
            for (int mi = 0; mi < 2; mi++) {
                const int r = wm + mi * 16 + (lane & 15);
                const int c = 2 * ks + (lane >> 4);
                const uint32_t byte = swz(r, c);
                ldsm4(ah[mi], sA + byte);
                ldsm4(al[mi], sA + 8192 + byte);
            }
#pragma unroll
            for (int ng = 0; ng < 4; ng++) {
                const int r = wn + ng * 16 + ((lane >> 4) << 3) + (lane & 7);
                const int c = 2 * ks + ((lane >> 3) & 1);
                const uint32_t byte = swz(r, c);
                uint32_t wh[4], wl[4];
                ldsm4(wh, sW + byte);
                ldsm4(wl, sW + 8192 + byte);
#pragma unroll
                for (int mi = 0; mi < 2; mi++)
#pragma unroll
                    for (int sub = 0; sub < 2; sub++) {
                        float* d = acc[mi * 8 + ng * 2 + sub];
                        mma16816(d, ah[mi], wh[2 * sub], wh[2 * sub + 1]);
                        mma16816(d, al[mi], wh[2 * sub], wh[2 * sub + 1]);
                        mma16816(d, ah[mi], wl[2 * sub], wl[2 * sub + 1]);
                    }
            }
        }
    };

    loadg(0);
    stores(0);
    __syncthreads();
    for (int c = 0; c < nch; c++) {
        if (c + 1 < nch) loadg(c + 1);
        do_mma(c & 1);
        if (c + 1 < nch) stores((c + 1) & 1);
        __syncthreads();
    }

    // ---- epilogue ----
#pragma unroll
    for (int mi = 0; mi < 2; mi++)
#pragma unroll
        for (int nj = 0; nj < 8; nj++) {
            const float* d = acc[mi * 8 + nj];
            const int gm = bm + wm + mi * 16 + (lane >> 2);
            const int gn = bn + wn + nj * 8 + (lane & 3) * 2;
            if (gn < N) {  // all N even -> gn+1 < N too
                const float b0 = __ldg(bias + gn), b1 = __ldg(bias + gn + 1);
                if (gm < M) {
                    float2 o;
                    o.x = d[0] + b0; o.y = d[1] + b1;
                    if (EPI == 1) { o.x = tanhf(o.x); o.y = tanhf(o.y); }
                    else if (EPI == 2) { o.x = fmaxf(o.x, 0.f); o.y = fmaxf(o.y, 0.f); }
                    *reinterpret_cast<float2*>(C + (size_t)gm * N + gn) = o;
                }
                if (gm + 8 < M) {
                    float2 o;
                    o.x = d[2] + b0; o.y = d[3] + b1;
                    if (EPI == 1) { o.x = tanhf(o.x); o.y = tanhf(o.y); }
                    else if (EPI == 2) { o.x = fmaxf(o.x, 0.f); o.y = fmaxf(o.y, 0.f); }
                    *reinterpret_cast<float2*>(C + (size_t)(gm + 8) * N + gn) = o;
                }
            }
        }
}

// ---------------- elementwise kernels (unchanged, proven) ----------------
__global__ void reduce_retrieved() {
    const size_t idx = (size_t)blockIdx.x * blockDim.x + threadIdx.x;
    if (idx >= (size_t)BSZ * PDIM) return;
    const int s = blockIdx.y;
    const int b = (int)(idx / PDIM), p = (int)(idx % PDIM);
    const float* base = g_Rout + (size_t)s * NRET * PDIM + (size_t)b * RNUM * PDIM + p;
    float sum = 0.f;
#pragma unroll
    for (int i = 0; i < RNUM; i++) sum += base[(size_t)i * PDIM];
    g_E[((size_t)(3 + s) * BSZ + b) * PDIM + p] = sum;
}

__global__ void build_means() {
    const size_t idx = (size_t)blockIdx.x * blockDim.x + threadIdx.x;
    if (idx >= (size_t)BSZ * PDIM) return;
    const int b = (int)(idx / PDIM), p = (int)(idx % PDIM);
    const float et = g_E[((size_t)0 * BSZ + b) * PDIM + p];
    const float ev = g_E[((size_t)1 * BSZ + b) * PDIM + p];
    const float eu = g_E[((size_t)2 * BSZ + b) * PDIM + p];
    const float srt = g_E[((size_t)3 * BSZ + b) * PDIM + p];
    const float srv = g_E[((size_t)4 * BSZ + b) * PDIM + p];
    const float sru = g_E[((size_t)5 * BSZ + b) * PDIM + p];
    float* row = g_M + (size_t)b * 4 * PDIM + p;
    row[0 * PDIM] = (et + ev + eu) * (1.f / 3.f);
    row[1 * PDIM] = (srt + et) * (1.f / 11.f);
    row[2 * PDIM] = (srv + ev) * (1.f / 11.f);
    row[3 * PDIM] = (sru + eu) * (1.f / 11.f);
}

__global__ void build_pair_means() {
    const int idx = blockIdx.x * blockDim.x + threadIdx.x;
    if (idx >= RNUM * PDIM) return;
    const int i = idx / PDIM, p = idx % PDIM;
    const float a = g_Rout[(size_t)0 * NRET * PDIM + (size_t)i * PDIM + p];
    const float c = g_Rout[(size_t)1 * NRET * PDIM + (size_t)i * PDIM + p];
    g_M[(size_t)(EDGE_ROWS + i) * PDIM + p] = 0.5f * (a + c);
}

__global__ void build_feat(const float* __restrict__ similarity,
                           const float* __restrict__ rlabel,
                           const float* __restrict__ lbl_w,
                           const float* __restrict__ lbl_b) {
    const int b = blockIdx.x;
    __shared__ float ssim[RNUM];
    __shared__ float s_lbl;
    if (threadIdx.x == 0) {
        float v[RNUM], mx = -1e30f;
#pragma unroll
        for (int i = 0; i < RNUM; i++) { v[i] = similarity[b * RNUM + i]; mx = fmaxf(mx, v[i]); }
        float sum = 0.f;
#pragma unroll
        for (int i = 0; i < RNUM; i++) { v[i] = expf(v[i] - mx); sum += v[i]; }
        float la = 0.f;
        const float inv = 1.f / sum;
#pragma unroll
        for (int i = 0; i < RNUM; i++) {
            v[i] *= inv; ssim[i] = v[i];
            la += v[i] * rlabel[b * RNUM + i];
        }
        s_lbl = la;
    }
    __syncthreads();
    const float* Yb = g_Y + (size_t)b * 4 * ZDIM;
    float* fb = g_feat + (size_t)b * FEATD;
    const float lagg = s_lbl;
    for (int z = threadIdx.x; z < ZDIM; z += blockDim.x) {
        const float Y0 = Yb[z], Y1 = Yb[ZDIM + z], Y2 = Yb[2 * ZDIM + z], Y3 = Yb[3 * ZDIM + z];
        fb[z]            = fmaxf(0.5f * (Y0 + Y1), 0.f);
        fb[ZDIM + z]     = fmaxf(0.5f * (Y0 + Y2), 0.f);
        fb[2 * ZDIM + z] = fmaxf(0.5f * (Y0 + Y3), 0.f);
        float rv, rt;
        if (b != 0) {
            rv = fmaxf(Y2, 0.f);
            rt = fmaxf(Y1, 0.f);
        } else {
            rv = 0.f; rt = 0.f;
#pragma unroll
            for (int i = 0; i < RNUM; i++) {
                const float yp = g_Y[(size_t)(EDGE_ROWS + i) * ZDIM + z];
                rt += ssim[i] * fmaxf(0.5f * (Y1 + yp), 0.f);
                rv += ssim[i] * fmaxf(0.5f * (Y2 + yp), 0.f);
            }
        }
        fb[3 * ZDIM + z] = rv;
        fb[4 * ZDIM + z] = rt;
        fb[5 * ZDIM + z] = fmaxf(Y3, 0.f);
        fb[6 * ZDIM + z] = fmaxf(lagg * lbl_w[z] + lbl_b[z], 0.f);
    }
}

__global__ void final_out(const float* __restrict__ p3_w, const float* __restrict__ p3_b,
                          float* __restrict__ out) {
    const int warp = (blockIdx.x * blockDim.x + threadIdx.x) >> 5;
    const int lane = threadIdx.x & 31;
    if (warp >= BSZ) return;
    const float* h = g_h2 + (size_t)warp * H2D;
    float s = 0.f;
    for (int j = lane; j < H2D; j += 32) s += h[j] * p3_w[j];
#pragma unroll
    for (int off = 16; off; off >>= 1) s += __shfl_xor_sync(0xffffffffu, s, off);
    if (lane == 0) out[warp] = 1.f / (1.f + expf(-(s + p3_b[0])));
}

// ---------------- host launcher ----------------
static inline dim3 ggrid(int M, int N) { return dim3((N + 127) / 128, (M + 127) / 128); }

extern "C" void kernel_launch(void* const* d_in, const int* in_sizes, int n_in,
                              void* d_out, int out_size) {
    const float* vis   = (const float*)d_in[0];
    const float* txt   = (const float*)d_in[1];
    const float* sim   = (const float*)d_in[2];
    const float* rvis  = (const float*)d_in[3];
    const float* rtxt  = (const float*)d_in[4];
    const float* rlbl  = (const float*)d_in[5];
    const float* usr   = (const float*)d_in[6];
    const float* rusr  = (const float*)d_in[7];
    const float* vis_w = (const float*)d_in[9],  *vis_b = (const float*)d_in[10];
    const float* txt_w = (const float*)d_in[11], *txt_b = (const float*)d_in[12];
    const float* usr_w = (const float*)d_in[13], *usr_b = (const float*)d_in[14];
    const float* rvis_w = (const float*)d_in[15], *rvis_b = (const float*)d_in[16];
    const float* rtxt_w = (const float*)d_in[17], *rtxt_b = (const float*)d_in[18];
    const float* rusr_w = (const float*)d_in[19], *rusr_b = (const float*)d_in[20];
    const float* hg_w  = (const float*)d_in[21], *hg_b = (const float*)d_in[22];
    const float* lbl_w = (const float*)d_in[23], *lbl_b = (const float*)d_in[24];
    const float* p1_w  = (const float*)d_in[25], *p1_b = (const float*)d_in[26];
    const float* p2_w  = (const float*)d_in[27], *p2_b = (const float*)d_in[28];
    const float* p3_w  = (const float*)d_in[29], *p3_b = (const float*)d_in[30];

    float *Rout, *E, *Mb, *Y, *feat, *h1, *h2;
    cudaGetSymbolAddress((void**)&Rout, g_Rout);
    cudaGetSymbolAddress((void**)&E, g_E);
    cudaGetSymbolAddress((void**)&Mb, g_M);
    cudaGetSymbolAddress((void**)&Y, g_Y);
    cudaGetSymbolAddress((void**)&feat, g_feat);
    cudaGetSymbolAddress((void**)&h1, g_h1);
    cudaGetSymbolAddress((void**)&h2, g_h2);

    cudaFuncSetAttribute(hgemm<0>, cudaFuncAttributeMaxDynamicSharedMemorySize, SMEM_BYTES);
    cudaFuncSetAttribute(hgemm<1>, cudaFuncAttributeMaxDynamicSharedMemorySize, SMEM_BYTES);
    cudaFuncSetAttribute(hgemm<2>, cudaFuncAttributeMaxDynamicSharedMemorySize, SMEM_BYTES);

    const dim3 blk(256);

    // 1) tanh embeddings (split-bf16 HMMA)
    hgemm<1><<<ggrid(BSZ, PDIM), blk, SMEM_BYTES>>>(txt, txt_w, txt_b, E + (size_t)0 * BSZ * PDIM, BSZ, PDIM, FDIM);
    hgemm<1><<<ggrid(BSZ, PDIM), blk, SMEM_BYTES>>>(vis, vis_w, vis_b, E + (size_t)1 * BSZ * PDIM, BSZ, PDIM, FDIM);
    hgemm<1><<<ggrid(BSZ, PDIM), blk, SMEM_BYTES>>>(usr, usr_w, usr_b, E + (size_t)2 * BSZ * PDIM, BSZ, PDIM, FDIM);
    hgemm<1><<<ggrid(NRET, PDIM), blk, SMEM_BYTES>>>(rtxt, rtxt_w, rtxt_b, Rout + (size_t)0 * NRET * PDIM, NRET, PDIM, FDIM);
    hgemm<1><<<ggrid(NRET, PDIM), blk, SMEM_BYTES>>>(rvis, rvis_w, rvis_b, Rout + (size_t)1 * NRET * PDIM, NRET, PDIM, FDIM);
    hgemm<1><<<ggrid(NRET, PDIM), blk, SMEM_BYTES>>>(rusr, rusr_w, rusr_b, Rout + (size_t)2 * NRET * PDIM, NRET, PDIM, FDIM);

    // 2) per-sample retrieved sums; 3) edge means
    reduce_retrieved<<<dim3(((size_t)BSZ * PDIM + 255) / 256, 3), blk>>>();
    build_means<<<((size_t)BSZ * PDIM + 255) / 256, blk>>>();
    build_pair_means<<<(RNUM * PDIM + 255) / 256, blk>>>();

    // 4) hypergraph projection
    hgemm<0><<<ggrid(M_ROWS, ZDIM), blk, SMEM_BYTES>>>(Mb, hg_w, hg_b, Y, M_ROWS, ZDIM, PDIM);

    // 5) feature assembly
    build_feat<<<BSZ, blk>>>(sim, rlbl, lbl_w, lbl_b);

    // 6) MLP head
    hgemm<2><<<ggrid(BSZ, H1D), blk, SMEM_BYTES>>>(feat, p1_w, p1_b, h1, BSZ, H1D, FEATD);
    hgemm<2><<<ggrid(BSZ, H2D), blk, SMEM_BYTES>>>(h1, p2_w, p2_b, h2, BSZ, H2D, H1D);
    final_out<<<(BSZ * 32 + 255) / 256, blk>>>(p3_w, p3_b, (float*)d_out);
}

// round 6
// speedup vs baseline: 2.4801x; 1.1388x over previous
#include <cuda_runtime.h>
#include <cuda_bf16.h>
#include <cstdint>
#include <math.h>

#define BSZ 4096
#define FDIM 768
#define PDIM 500
#define ZDIM 300
#define RNUM 10
#define NRET (BSZ * RNUM)          // 40960
#define EDGE_ROWS (BSZ * 4)        // 16384
#define M_ROWS (EDGE_ROWS + RNUM)  // 16394
#define FEATD 2100
#define H1D 800
#define H2D 200

// ---------------- scratch (device globals) ----------------
__device__ float g_Rout[3ull * NRET * PDIM];
__device__ float g_E[3ull * BSZ * PDIM];       // emb_t, emb_v, emb_u only
__device__ float g_M[(size_t)M_ROWS * PDIM];
__device__ float g_Y[(size_t)M_ROWS * ZDIM];
__device__ float g_feat[(size_t)BSZ * FEATD];
__device__ float g_h1[(size_t)BSZ * H1D];
__device__ float g_h2[(size_t)BSZ * H2D];

// ---------------- warp-MMA helpers ----------------
__device__ __forceinline__ uint32_t smem_u32(const void* p) {
    uint32_t a;
    asm("{ .reg .u64 t; cvta.to.shared.u64 t, %1; cvt.u32.u64 %0, t; }" : "=r"(a) : "l"(p));
    return a;
}
__device__ __forceinline__ void ldsm4(uint32_t* r, uint32_t addr) {
    asm volatile("ldmatrix.sync.aligned.m8n8.x4.shared.b16 {%0,%1,%2,%3}, [%4];"
                 : "=r"(r[0]), "=r"(r[1]), "=r"(r[2]), "=r"(r[3]) : "r"(addr));
}
__device__ __forceinline__ void mma16816(float* d, const uint32_t* a, uint32_t b0, uint32_t b1) {
    asm volatile(
        "mma.sync.aligned.m16n8k16.row.col.f32.bf16.bf16.f32 "
        "{%0,%1,%2,%3}, {%4,%5,%6,%7}, {%8,%9}, {%0,%1,%2,%3};"
        : "+f"(d[0]), "+f"(d[1]), "+f"(d[2]), "+f"(d[3])
        : "r"(a[0]), "r"(a[1]), "r"(a[2]), "r"(a[3]), "r"(b0), "r"(b1));
}
__device__ __forceinline__ uint32_t packbf(__nv_bfloat16 x, __nv_bfloat16 y) {
    __nv_bfloat162 t; t.x = x; t.y = y;
    return *reinterpret_cast<uint32_t*>(&t);
}
// 16B-chunk XOR swizzle for 64B rows
__device__ __forceinline__ uint32_t swz(int row, int chunk) {
    return (uint32_t)(row * 64 + ((chunk ^ ((row >> 1) & 3)) << 4));
}

#define STAGE_BYTES 32768  // Ahi 8K | Alo 8K | Whi 8K | Wlo 8K
#define SMEM_BYTES 65536

// ============ split-bf16 HMMA GEMM: C = epi(A[M,K] @ W[N,K]^T + bias) ============
// 512 threads, 16 warps, block tile 128x128, warp tile 32x32, double-buffered.
// 3-pass: D = Ahi*Whi + Alo*Whi + Ahi*Wlo  (error ~2^-24 class)
template <int EPI>  // 0=none, 1=tanh, 2=relu
__global__ void __launch_bounds__(512, 1)
hgemm(const float* __restrict__ A, const float* __restrict__ W,
      const float* __restrict__ bias, float* __restrict__ C,
      int M, int N, int K) {
    extern __shared__ char smem[];
    const uint32_t sbase = smem_u32(smem);
    const int tid = threadIdx.x, wid = tid >> 5, lane = tid & 31;
    const int bm = blockIdx.y * 128, bn = blockIdx.x * 128;
    const int wm = (wid & 3) * 32;   // warp m offset
    const int wn = (wid >> 2) * 32;  // warp n offset

    float acc[8][4];
#pragma unroll
    for (int i = 0; i < 8; i++)
#pragma unroll
        for (int j = 0; j < 4; j++) acc[i][j] = 0.f;

    const int nch = (K + 31) >> 5;
    float4 pa[2], pw[2];

    // per-chunk global fetch: A/W tiles are 128 rows x 8 float4 = 1024 slots, 512 thr -> 2 each
    auto loadg = [&](int c) {
        const int kk0 = c << 5;
#pragma unroll
        for (int i = 0; i < 2; i++) {
            const int slot = tid + (i << 9);
            const int row = slot >> 3, c4 = slot & 7;
            const int gk = kk0 + (c4 << 2);
            const int gm = bm + row;
            float4 v = make_float4(0.f, 0.f, 0.f, 0.f);
            if (gm < M) {
                if (gk + 4 <= K) v = *reinterpret_cast<const float4*>(A + (size_t)gm * K + gk);
                else {
                    float t[4] = {0.f, 0.f, 0.f, 0.f};
                    for (int q = 0; q < 4; q++) if (gk + q < K) t[q] = A[(size_t)gm * K + gk + q];
                    v = make_float4(t[0], t[1], t[2], t[3]);
                }
            }
            pa[i] = v;
            const int gn = bn + row;
            float4 w = make_float4(0.f, 0.f, 0.f, 0.f);
            if (gn < N) {
                if (gk + 4 <= K) w = *reinterpret_cast<const float4*>(W + (size_t)gn * K + gk);
                else {
                    float t[4] = {0.f, 0.f, 0.f, 0.f};
                    for (int q = 0; q < 4; q++) if (gk + q < K) t[q] = W[(size_t)gn * K + gk + q];
                    w = make_float4(t[0], t[1], t[2], t[3]);
                }
            }
            pw[i] = w;
        }
    };

    auto stores = [&](int st) {
        char* base = smem + st * STAGE_BYTES;
#pragma unroll
        for (int i = 0; i < 2; i++) {
            const int slot = tid + (i << 9);
            const int row = slot >> 3, c4 = slot & 7;
            const uint32_t byte = swz(row, c4 >> 1) + ((c4 & 1) << 3);
#pragma unroll
            for (int half = 0; half < 2; half++) {
                const float4 v = half ? pw[i] : pa[i];
                const __nv_bfloat16 h0 = __float2bfloat16(v.x), h1 = __float2bfloat16(v.y);
                const __nv_bfloat16 h2 = __float2bfloat16(v.z), h3 = __float2bfloat16(v.w);
                const __nv_bfloat16 l0 = __float2bfloat16(v.x - __bfloat162float(h0));
                const __nv_bfloat16 l1 = __float2bfloat16(v.y - __bfloat162float(h1));
                const __nv_bfloat16 l2 = __float2bfloat16(v.z - __bfloat162float(h2));
                const __nv_bfloat16 l3 = __float2bfloat16(v.w - __bfloat162float(h3));
                uint2 hi, lo;
                hi.x = packbf(h0, h1); hi.y = packbf(h2, h3);
                lo.x = packbf(l0, l1); lo.y = packbf(l2, l3);
                char* r = base + half * 16384;
                *reinterpret_cast<uint2*>(r + byte) = hi;
                *reinterpret_cast<uint2*>(r + 8192 + byte) = lo;
            }
        }
    };

    auto do_mma = [&](int st) {
        const uint32_t sA = sbase + st * STAGE_BYTES;
        const uint32_t sW = sA + 16384;
#pragma unroll
        for (int ks = 0; ks < 2; ks++) {
            uint32_t ah[2][4], al[2][4];
#pragma unroll
            for (int mi = 0; mi < 2; mi++) {
                const int r = wm + mi * 16 + (lane & 15);
                const int c = 2 * ks + (lane >> 4);
                const uint32_t byte = swz(r, c);
                ldsm4(ah[mi], sA + byte);
                ldsm4(al[mi], sA + 8192 + byte);
            }
#pragma unroll
            for (int ng = 0; ng < 2; ng++) {
                const int r = wn + ng * 16 + ((lane >> 4) << 3) + (lane & 7);
                const int c = 2 * ks + ((lane >> 3) & 1);
                const uint32_t byte = swz(r, c);
                uint32_t wh[4], wl[4];
                ldsm4(wh, sW + byte);
                ldsm4(wl, sW + 8192 + byte);
#pragma unroll
                for (int mi = 0; mi < 2; mi++)
#pragma unroll
                    for (int sub = 0; sub < 2; sub++) {
                        float* d = acc[mi * 4 + ng * 2 + sub];
                        mma16816(d, ah[mi], wh[2 * sub], wh[2 * sub + 1]);
                        mma16816(d, al[mi], wh[2 * sub], wh[2 * sub + 1]);
                        mma16816(d, ah[mi], wl[2 * sub], wl[2 * sub + 1]);
                    }
            }
        }
    };

    loadg(0);
    stores(0);
    __syncthreads();
    for (int c = 0; c < nch; c++) {
        if (c + 1 < nch) loadg(c + 1);
        do_mma(c & 1);
        if (c + 1 < nch) stores((c + 1) & 1);
        __syncthreads();
    }

    // ---- epilogue: warp covers rows wm..wm+31, cols wn..wn+31 ----
#pragma unroll
    for (int mi = 0; mi < 2; mi++)
#pragma unroll
        for (int nj = 0; nj < 4; nj++) {
            const float* d = acc[mi * 4 + nj];
            const int gm = bm + wm + mi * 16 + (lane >> 2);
            const int gn = bn + wn + nj * 8 + (lane & 3) * 2;
            if (gn < N) {  // N always even
                const float b0 = __ldg(bias + gn), b1 = __ldg(bias + gn + 1);
                if (gm < M) {
                    float2 o;
                    o.x = d[0] + b0; o.y = d[1] + b1;
                    if (EPI == 1) { o.x = tanhf(o.x); o.y = tanhf(o.y); }
                    else if (EPI == 2) { o.x = fmaxf(o.x, 0.f); o.y = fmaxf(o.y, 0.f); }
                    *reinterpret_cast<float2*>(C + (size_t)gm * N + gn) = o;
                }
                if (gm + 8 < M) {
                    float2 o;
                    o.x = d[2] + b0; o.y = d[3] + b1;
                    if (EPI == 1) { o.x = tanhf(o.x); o.y = tanhf(o.y); }
                    else if (EPI == 2) { o.x = fmaxf(o.x, 0.f); o.y = fmaxf(o.y, 0.f); }
                    *reinterpret_cast<float2*>(C + (size_t)(gm + 8) * N + gn) = o;
                }
            }
        }
}

// ---------------- fused retrieved-sum + edge-mean kernel (float4) ----------------
__global__ void build_means_fused() {
    const int idx = blockIdx.x * blockDim.x + threadIdx.x;
    if (idx >= BSZ * (PDIM / 4)) return;
    const int b = idx / (PDIM / 4), p4 = (idx % (PDIM / 4)) * 4;

    const float4 et = *reinterpret_cast<const float4*>(g_E + ((size_t)0 * BSZ + b) * PDIM + p4);
    const float4 ev = *reinterpret_cast<const float4*>(g_E + ((size_t)1 * BSZ + b) * PDIM + p4);
    const float4 eu = *reinterpret_cast<const float4*>(g_E + ((size_t)2 * BSZ + b) * PDIM + p4);

    float4 S[3];
#pragma unroll
    for (int s = 0; s < 3; s++) {
        const float* base = g_Rout + (size_t)s * NRET * PDIM + (size_t)b * RNUM * PDIM + p4;
        float4 acc = make_float4(0.f, 0.f, 0.f, 0.f);
#pragma unroll
        for (int i = 0; i < RNUM; i++) {
            const float4 v = *reinterpret_cast<const float4*>(base + (size_t)i * PDIM);
            acc.x += v.x; acc.y += v.y; acc.z += v.z; acc.w += v.w;
        }
        S[s] = acc;
    }
    float* row = g_M + (size_t)b * 4 * PDIM + p4;
    const float i3 = 1.f / 3.f, i11 = 1.f / 11.f;
    float4 o0, o1, o2, o3;
    o0.x = (et.x + ev.x + eu.x) * i3; o0.y = (et.y + ev.y + eu.y) * i3;
    o0.z = (et.z + ev.z + eu.z) * i3; o0.w = (et.w + ev.w + eu.w) * i3;
    o1.x = (S[0].x + et.x) * i11; o1.y = (S[0].y + et.y) * i11;
    o1.z = (S[0].z + et.z) * i11; o1.w = (S[0].w + et.w) * i11;
    o2.x = (S[1].x + ev.x) * i11; o2.y = (S[1].y + ev.y) * i11;
    o2.z = (S[1].z + ev.z) * i11; o2.w = (S[1].w + ev.w) * i11;
    o3.x = (S[2].x + eu.x) * i11; o3.y = (S[2].y + eu.y) * i11;
    o3.z = (S[2].z + eu.z) * i11; o3.w = (S[2].w + eu.w) * i11;
    *reinterpret_cast<float4*>(row + 0 * PDIM) = o0;
    *reinterpret_cast<float4*>(row + 1 * PDIM) = o1;
    *reinterpret_cast<float4*>(row + 2 * PDIM) = o2;
    *reinterpret_cast<float4*>(row + 3 * PDIM) = o3;
}

__global__ void build_pair_means() {
    const int idx = blockIdx.x * blockDim.x + threadIdx.x;
    if (idx >= RNUM * PDIM) return;
    const int i = idx / PDIM, p = idx % PDIM;
    const float a = g_Rout[(size_t)0 * NRET * PDIM + (size_t)i * PDIM + p];
    const float c = g_Rout[(size_t)1 * NRET * PDIM + (size_t)i * PDIM + p];
    g_M[(size_t)(EDGE_ROWS + i) * PDIM + p] = 0.5f * (a + c);
}

__global__ void build_feat(const float* __restrict__ similarity,
                           const float* __restrict__ rlabel,
                           const float* __restrict__ lbl_w,
                           const float* __restrict__ lbl_b) {
    const int b = blockIdx.x;
    __shared__ float ssim[RNUM];
    __shared__ float s_lbl;
    if (threadIdx.x == 0) {
        float v[RNUM], mx = -1e30f;
#pragma unroll
        for (int i = 0; i < RNUM; i++) { v[i] = similarity[b * RNUM + i]; mx = fmaxf(mx, v[i]); }
        float sum = 0.f;
#pragma unroll
        for (int i = 0; i < RNUM; i++) { v[i] = expf(v[i] - mx); sum += v[i]; }
        float la = 0.f;
        const float inv = 1.f / sum;
#pragma unroll
        for (int i = 0; i < RNUM; i++) {
            v[i] *= inv; ssim[i] = v[i];
            la += v[i] * rlabel[b * RNUM + i];
        }
        s_lbl = la;
    }
    __syncthreads();
    const float* Yb = g_Y + (size_t)b * 4 * ZDIM;
    float* fb = g_feat + (size_t)b * FEATD;
    const float lagg = s_lbl;
    for (int z = threadIdx.x; z < ZDIM; z += blockDim.x) {
        const float Y0 = Yb[z], Y1 = Yb[ZDIM + z], Y2 = Yb[2 * ZDIM + z], Y3 = Yb[3 * ZDIM + z];
        fb[z]            = fmaxf(0.5f * (Y0 + Y1), 0.f);
        fb[ZDIM + z]     = fmaxf(0.5f * (Y0 + Y2), 0.f);
        fb[2 * ZDIM + z] = fmaxf(0.5f * (Y0 + Y3), 0.f);
        float rv, rt;
        if (b != 0) {
            rv = fmaxf(Y2, 0.f);
            rt = fmaxf(Y1, 0.f);
        } else {
            rv = 0.f; rt = 0.f;
#pragma unroll
            for (int i = 0; i < RNUM; i++) {
                const float yp = g_Y[(size_t)(EDGE_ROWS + i) * ZDIM + z];
                rt += ssim[i] * fmaxf(0.5f * (Y1 + yp), 0.f);
                rv += ssim[i] * fmaxf(0.5f * (Y2 + yp), 0.f);
            }
        }
        fb[3 * ZDIM + z] = rv;
        fb[4 * ZDIM + z] = rt;
        fb[5 * ZDIM + z] = fmaxf(Y3, 0.f);
        fb[6 * ZDIM + z] = fmaxf(lagg * lbl_w[z] + lbl_b[z], 0.f);
    }
}

__global__ void final_out(const float* __restrict__ p3_w, const float* __restrict__ p3_b,
                          float* __restrict__ out) {
    const int warp = (blockIdx.x * blockDim.x + threadIdx.x) >> 5;
    const int lane = threadIdx.x & 31;
    if (warp >= BSZ) return;
    const float* h = g_h2 + (size_t)warp * H2D;
    float s = 0.f;
    for (int j = lane; j < H2D; j += 32) s += h[j] * p3_w[j];
#pragma unroll
    for (int off = 16; off; off >>= 1) s += __shfl_xor_sync(0xffffffffu, s, off);
    if (lane == 0) out[warp] = 1.f / (1.f + expf(-(s + p3_b[0])));
}

// ---------------- host launcher ----------------
static inline dim3 ggrid(int M, int N) { return dim3((N + 127) / 128, (M + 127) / 128); }

extern "C" void kernel_launch(void* const* d_in, const int* in_sizes, int n_in,
                              void* d_out, int out_size) {
    const float* vis   = (const float*)d_in[0];
    const float* txt   = (const float*)d_in[1];
    const float* sim   = (const float*)d_in[2];
    const float* rvis  = (const float*)d_in[3];
    const float* rtxt  = (const float*)d_in[4];
    const float* rlbl  = (const float*)d_in[5];
    const float* usr   = (const float*)d_in[6];
    const float* rusr  = (const float*)d_in[7];
    const float* vis_w = (const float*)d_in[9],  *vis_b = (const float*)d_in[10];
    const float* txt_w = (const float*)d_in[11], *txt_b = (const float*)d_in[12];
    const float* usr_w = (const float*)d_in[13], *usr_b = (const float*)d_in[14];
    const float* rvis_w = (const float*)d_in[15], *rvis_b = (const float*)d_in[16];
    const float* rtxt_w = (const float*)d_in[17], *rtxt_b = (const float*)d_in[18];
    const float* rusr_w = (const float*)d_in[19], *rusr_b = (const float*)d_in[20];
    const float* hg_w  = (const float*)d_in[21], *hg_b = (const float*)d_in[22];
    const float* lbl_w = (const float*)d_in[23], *lbl_b = (const float*)d_in[24];
    const float* p1_w  = (const float*)d_in[25], *p1_b = (const float*)d_in[26];
    const float* p2_w  = (const float*)d_in[27], *p2_b = (const float*)d_in[28];
    const float* p3_w  = (const float*)d_in[29], *p3_b = (const float*)d_in[30];

    float *Rout, *E, *Mb, *Y, *feat, *h1, *h2;
    cudaGetSymbolAddress((void**)&Rout, g_Rout);
    cudaGetSymbolAddress((void**)&E, g_E);
    cudaGetSymbolAddress((void**)&Mb, g_M);
    cudaGetSymbolAddress((void**)&Y, g_Y);
    cudaGetSymbolAddress((void**)&feat, g_feat);
    cudaGetSymbolAddress((void**)&h1, g_h1);
    cudaGetSymbolAddress((void**)&h2, g_h2);

    cudaFuncSetAttribute(hgemm<0>, cudaFuncAttributeMaxDynamicSharedMemorySize, SMEM_BYTES);
    cudaFuncSetAttribute(hgemm<1>, cudaFuncAttributeMaxDynamicSharedMemorySize, SMEM_BYTES);
    cudaFuncSetAttribute(hgemm<2>, cudaFuncAttributeMaxDynamicSharedMemorySize, SMEM_BYTES);

    const dim3 blk(512);

    // 1) tanh embeddings (split-bf16 HMMA, 16 warps)
    hgemm<1><<<ggrid(BSZ, PDIM), blk, SMEM_BYTES>>>(txt, txt_w, txt_b, E + (size_t)0 * BSZ * PDIM, BSZ, PDIM, FDIM);
    hgemm<1><<<ggrid(BSZ, PDIM), blk, SMEM_BYTES>>>(vis, vis_w, vis_b, E + (size_t)1 * BSZ * PDIM, BSZ, PDIM, FDIM);
    hgemm<1><<<ggrid(BSZ, PDIM), blk, SMEM_BYTES>>>(usr, usr_w, usr_b, E + (size_t)2 * BSZ * PDIM, BSZ, PDIM, FDIM);
    hgemm<1><<<ggrid(NRET, PDIM), blk, SMEM_BYTES>>>(rtxt, rtxt_w, rtxt_b, Rout + (size_t)0 * NRET * PDIM, NRET, PDIM, FDIM);
    hgemm<1><<<ggrid(NRET, PDIM), blk, SMEM_BYTES>>>(rvis, rvis_w, rvis_b, Rout + (size_t)1 * NRET * PDIM, NRET, PDIM, FDIM);
    hgemm<1><<<ggrid(NRET, PDIM), blk, SMEM_BYTES>>>(rusr, rusr_w, rusr_b, Rout + (size_t)2 * NRET * PDIM, NRET, PDIM, FDIM);

    // 2+3) fused retrieved sums + edge means
    build_means_fused<<<(BSZ * (PDIM / 4) + 255) / 256, 256>>>();
    build_pair_means<<<(RNUM * PDIM + 255) / 256, 256>>>();

    // 4) hypergraph projection
    hgemm<0><<<ggrid(M_ROWS, ZDIM), blk, SMEM_BYTES>>>(Mb, hg_w, hg_b, Y, M_ROWS, ZDIM, PDIM);

    // 5) feature assembly
    build_feat<<<BSZ, 256>>>(sim, rlbl, lbl_w, lbl_b);

    // 6) MLP head
    hgemm<2><<<ggrid(BSZ, H1D), blk, SMEM_BYTES>>>(feat, p1_w, p1_b, h1, BSZ, H1D, FEATD);
    hgemm<2><<<ggrid(BSZ, H2D), blk, SMEM_BYTES>>>(h1, p2_w, p2_b, h2, BSZ, H2D, H1D);
    final_out<<<(BSZ * 32 + 255) / 256, 256>>>(p3_w, p3_b, (float*)d_out);
}